// round 16
// baseline (speedup 1.0000x reference)
#include <cuda_runtime.h>
#include <cuda_bf16.h>
#include <math.h>
#include <float.h>
#include <stdint.h>

#define S_  4096
#define H_  1024
#define NH_ 2
#define HD_ 512
#define DS_ 64
#define K3  (3 * H_)    // 3072
#define KQK (3 * HD_)   // 1536
#define KPV (3 * S_)    // 12288

// ---------------- scratch (device globals; no allocations allowed) ----------
__device__ float g_semb[H_];
__device__ float g_V[(size_t)S_ * H_];
__device__ float g_logits2[(size_t)NH_ * S_ * S_];
__device__ float g_out[(size_t)S_ * H_];
__device__ unsigned char g_maskb[S_];
__device__ int g_cnt, g_cntpad;
__device__ int g_idx[S_];
__device__ int g_pos[S_];
__device__ float g_pvp[(size_t)6 * S_ * HD_];   // PV split-K partials (fp32)

__device__ __nv_bfloat16 g_ins_s [(size_t)S_ * 2 * H_];
__device__ __nv_bfloat16 g_kvin_s[(size_t)S_ * 2 * H_];
__device__ __nv_bfloat16 g_Wq_s[(size_t)H_ * 2 * H_];
__device__ __nv_bfloat16 g_Wk_s[(size_t)H_ * 2 * H_];
__device__ __nv_bfloat16 g_Wv_s[(size_t)H_ * 2 * H_];
__device__ __nv_bfloat16 g_Wo_s[(size_t)H_ * 2 * H_];
__device__ __nv_bfloat16 g_Qs[(size_t)S_ * NH_ * 2 * HD_];
__device__ __nv_bfloat16 g_Ks[(size_t)S_ * NH_ * 2 * HD_];
__device__ __nv_bfloat16 g_Ps2[(size_t)NH_ * S_ * 2 * S_];
__device__ __nv_bfloat16 g_Vts[(size_t)NH_ * HD_ * 2 * S_];
__device__ __nv_bfloat16 g_ctxs[(size_t)S_ * 2 * H_];

// ===================== helpers ===============================================
__device__ __forceinline__ uint32_t smem_u32(const void* p) {
    uint32_t a;
    asm("{ .reg .u64 t; cvta.to.shared.u64 t, %1; cvt.u32.u64 %0, t; }" : "=r"(a) : "l"(p));
    return a;
}
#define CP_ASYNC16(dst, src) \
    asm volatile("cp.async.cg.shared.global [%0], [%1], 16;" :: "r"(dst), "l"(src))
#define CP_COMMIT() asm volatile("cp.async.commit_group;")
#define CP_WAIT(n)  asm volatile("cp.async.wait_group %0;" :: "n"(n))

__device__ __forceinline__ void ldsm_x4(uint32_t& r0, uint32_t& r1, uint32_t& r2, uint32_t& r3,
                                        uint32_t addr) {
    asm volatile("ldmatrix.sync.aligned.m8n8.x4.shared.b16 {%0,%1,%2,%3}, [%4];"
                 : "=r"(r0), "=r"(r1), "=r"(r2), "=r"(r3) : "r"(addr));
}
__device__ __forceinline__ void mma_16816(float* c, const uint32_t* a, uint32_t b0, uint32_t b1) {
    asm volatile("mma.sync.aligned.m16n8k16.row.col.f32.bf16.bf16.f32 "
                 "{%0,%1,%2,%3}, {%4,%5,%6,%7}, {%8,%9}, {%0,%1,%2,%3};"
                 : "+f"(c[0]), "+f"(c[1]), "+f"(c[2]), "+f"(c[3])
                 : "r"(a[0]), "r"(a[1]), "r"(a[2]), "r"(a[3]), "r"(b0), "r"(b1));
}
__device__ __forceinline__ void split2(float x, __nv_bfloat16& hi, __nv_bfloat16& lo) {
    hi = __float2bfloat16(x);
    lo = __float2bfloat16(x - __bfloat162float(hi));
}
__device__ __forceinline__ void split4_store(__nv_bfloat16* dHi, __nv_bfloat16* dLo, float4 v) {
    __nv_bfloat16 h0, h1, h2, h3, l0, l1, l2, l3;
    split2(v.x, h0, l0); split2(v.y, h1, l1);
    split2(v.z, h2, l2); split2(v.w, h3, l3);
    __nv_bfloat162 ha, hb, la, lb;
    ha.x = h0; ha.y = h1; hb.x = h2; hb.y = h3;
    la.x = l0; la.y = l1; lb.x = l2; lb.y = l3;
    uint2 hp, lp;
    hp.x = *reinterpret_cast<uint32_t*>(&ha); hp.y = *reinterpret_cast<uint32_t*>(&hb);
    lp.x = *reinterpret_cast<uint32_t*>(&la); lp.y = *reinterpret_cast<uint32_t*>(&lb);
    *reinterpret_cast<uint2*>(dHi) = hp;
    *reinterpret_cast<uint2*>(dLo) = lp;
}
__device__ __forceinline__ uint32_t toff(int r, int c8) {
    return (uint32_t)(r * 128 + ((c8 ^ (r & 7)) << 4));
}

// ===================== bf16 HMMA GEMM ========================================
// Logical A' = [Ahi|Alo|Ahi], B' = [Bhi|Bhi|Blo] from physical [hi|lo] via
// per-stage K remap. CTA 128x128, BK=64, 4 warps (64x64), 3-stage cp.async,
// 2 CTA/SM, hoisted row offsets.
// MODE 0: generic fp32 C (+ optional z-gather/early-exit via gidx)
// MODE 5: fused Q/K/V projection (z: 0=Q split, 1=K split, 2=V fp32)
// MODE 6: PV split-K (z: 0,1 = h0 K-chunks; 2..5 = h1 K-chunks) -> fp32 partial
#define GEMM_SMEM (3 * 32768)

template <int MODE>
__global__ __launch_bounds__(128, 2)
void bf16_gemm_kernel(const __nv_bfloat16* __restrict__ A, int lda, size_t sAz,
                      const __nv_bfloat16* __restrict__ B, int ldb, size_t sBz,
                      float* __restrict__ C, int ldc, size_t sCz,
                      __nv_bfloat16* __restrict__ CS,
                      int Kp, float alpha,
                      const int* __restrict__ gidx, int dynz) {
    extern __shared__ char smem[];
    const uint32_t sb = smem_u32(smem);
    const int tid = threadIdx.x, lane = tid & 31, wid = tid >> 5;
    const int row0 = blockIdx.y * 128, col0 = blockIdx.x * 128;
    const int z = blockIdx.z;

    int Kth, s0, NSc;   // logical K third, start stage, stage count
    const int* gmap = nullptr;
    int hh = 0;
    if (MODE == 6) {
        hh = (z < 2) ? 0 : 1;
        Kth = (hh == 0) ? g_cntpad : S_;
        const int NStot = (3 * Kth) >> 6;
        if (hh == 0) { NSc = NStot >> 1; s0 = z * NSc; }
        else         { NSc = NStot >> 2; s0 = (z - 2) * NSc; }
        A = g_Ps2 + (size_t)hh * S_ * 2 * S_;  lda = 2 * S_;
        B = g_Vts + (size_t)hh * HD_ * 2 * S_; ldb = 2 * S_;
    } else {
        Kth = Kp / 3;
        gmap = (gidx != nullptr && z == 0) ? gidx : nullptr;
        if (gmap != nullptr && col0 >= g_cntpad) return;
        s0 = 0; NSc = (3 * Kth) >> 6;
        if (MODE == 5) {
            A = (z == 0) ? g_ins_s : g_kvin_s;
            B = (z == 0) ? g_Wq_s : (z == 1) ? g_Wk_s : g_Wv_s;
            lda = 2 * H_; ldb = 2 * H_;
        } else {
            A += (size_t)z * sAz;  B += (size_t)z * sBz;  C += (size_t)z * sCz;
        }
    }

    const int wm = wid & 1, wn = wid >> 1;
    const int m_base = wm * 64, n_base = wn * 64;
    const int lr = tid >> 3, lc = tid & 7;
    const int g = lane >> 3, ri = lane & 7;
    const int a_r = ri + ((g & 1) << 3), a_c = g >> 1;
    const int b_r = ri + ((g >> 1) << 3), b_c = g & 1;

    size_t aOff[8], bOff[8];
#pragma unroll
    for (int i = 0; i < 8; i++) {
        int r = lr + 16 * i;
        aOff[i] = (size_t)(row0 + r) * lda + lc * 8;
        int rb_ = col0 + r;
        if (gmap != nullptr) rb_ = gmap[rb_];
        bOff[i] = (size_t)rb_ * ldb + lc * 8;
    }

    float acc[4][8][4];
#pragma unroll
    for (int i = 0; i < 4; i++)
#pragma unroll
        for (int j = 0; j < 8; j++)
#pragma unroll
            for (int k = 0; k < 4; k++) acc[i][j][k] = 0.f;

    auto load_stage = [&](int s) {
        const int k0 = s << 6;
        const int kA = (k0 < 2 * Kth) ? k0 : k0 - 2 * Kth;
        const int kB = (k0 < Kth) ? k0 : k0 - Kth;
        const uint32_t ba = sb + (s % 3) * 32768;
        const uint32_t bb = ba + 16384;
#pragma unroll
        for (int i = 0; i < 8; i++) {
            uint32_t so = toff(lr + 16 * i, lc);
            CP_ASYNC16(ba + so, A + aOff[i] + kA);
            CP_ASYNC16(bb + so, B + bOff[i] + kB);
        }
        CP_COMMIT();
    };

    const int sEnd = s0 + NSc;
    load_stage(s0);
    load_stage(s0 + 1);

    for (int s = s0; s < sEnd; s++) {
        if (s == sEnd - 1) { CP_WAIT(0); } else { CP_WAIT(1); }
        __syncthreads();

        const uint32_t ba = sb + (s % 3) * 32768;
        const uint32_t bb = ba + 16384;
#pragma unroll
        for (int ks = 0; ks < 4; ks++) {
            const int c8k = ks << 1;
            uint32_t afr[4][4];
#pragma unroll
            for (int mi = 0; mi < 4; mi++)
                ldsm_x4(afr[mi][0], afr[mi][1], afr[mi][2], afr[mi][3],
                        ba + toff(m_base + mi * 16 + a_r, c8k + a_c));
            uint32_t bfr[4][4];
#pragma unroll
            for (int p = 0; p < 4; p++)
                ldsm_x4(bfr[p][0], bfr[p][1], bfr[p][2], bfr[p][3],
                        bb + toff(n_base + p * 16 + b_r, c8k + b_c));
#pragma unroll
            for (int mi = 0; mi < 4; mi++)
#pragma unroll
                for (int nj = 0; nj < 8; nj++) {
                    const uint32_t* bp = bfr[nj >> 1];
                    if (nj & 1) mma_16816(acc[mi][nj], afr[mi], bp[2], bp[3]);
                    else        mma_16816(acc[mi][nj], afr[mi], bp[0], bp[1]);
                }
        }
        if (s + 2 < sEnd) load_stage(s + 2);
    }

    // ---- epilogue ----
    const int er = lane >> 2, ec = (lane & 3) << 1;

    auto store_pair = [&](int row, int col, float vx, float vy) {
        if (MODE == 6) {
            float* dst = g_pvp + (size_t)z * S_ * HD_;
            float2 v; v.x = vx; v.y = vy;
            *reinterpret_cast<float2*>(dst + (size_t)row * HD_ + col) = v;
        } else if (MODE == 5) {
            if (z == 2) {
                float2 v; v.x = vx; v.y = vy;
                *reinterpret_cast<float2*>(g_V + (size_t)row * H_ + col) = v;
            } else {
                __nv_bfloat16* dst = (z == 0) ? g_Qs : g_Ks;
                __nv_bfloat16 hx, lx, hy, ly;
                split2(vx, hx, lx);
                split2(vy, hy, ly);
                __nv_bfloat162 h2, l2;
                h2.x = hx; h2.y = hy; l2.x = lx; l2.y = ly;
                int h = col >> 9, jh = col & (HD_ - 1);
                size_t base = (size_t)row * (NH_ * 2 * HD_) + (size_t)h * (2 * HD_);
                *reinterpret_cast<__nv_bfloat162*>(dst + base + jh)        = h2;
                *reinterpret_cast<__nv_bfloat162*>(dst + base + HD_ + jh)  = l2;
            }
        } else {
            float2 v; v.x = vx; v.y = vy;
            *reinterpret_cast<float2*>(C + (size_t)row * ldc + col) = v;
        }
    };

#pragma unroll
    for (int mi = 0; mi < 4; mi++) {
#pragma unroll
        for (int nj = 0; nj < 8; nj++) {
            int row = row0 + m_base + mi * 16 + er;
            int col = col0 + n_base + nj * 8 + ec;
            store_pair(row,     col, acc[mi][nj][0] * alpha, acc[mi][nj][1] * alpha);
            store_pair(row + 8, col, acc[mi][nj][2] * alpha, acc[mi][nj][3] * alpha);
        }
    }
}

// ===================== PV combine: fixed-order sum + ctx split ===============
__global__ void pv_combine_kernel() {
    size_t i = (size_t)blockIdx.x * blockDim.x + threadIdx.x;
    int row = (int)(i / (H_ / 4)), c4 = (int)(i % (H_ / 4)) * 4;
    int h = c4 >> 9, n = c4 & (HD_ - 1);
    size_t off = (size_t)row * HD_ + n;
    float4 acc;
    if (h == 0) {
        const float4 a = *reinterpret_cast<const float4*>(g_pvp + 0 * (size_t)S_ * HD_ + off);
        const float4 b = *reinterpret_cast<const float4*>(g_pvp + 1 * (size_t)S_ * HD_ + off);
        acc.x = a.x + b.x; acc.y = a.y + b.y; acc.z = a.z + b.z; acc.w = a.w + b.w;
    } else {
        const float4 a = *reinterpret_cast<const float4*>(g_pvp + 2 * (size_t)S_ * HD_ + off);
        const float4 b = *reinterpret_cast<const float4*>(g_pvp + 3 * (size_t)S_ * HD_ + off);
        const float4 c = *reinterpret_cast<const float4*>(g_pvp + 4 * (size_t)S_ * HD_ + off);
        const float4 d = *reinterpret_cast<const float4*>(g_pvp + 5 * (size_t)S_ * HD_ + off);
        acc.x = ((a.x + b.x) + c.x) + d.x;
        acc.y = ((a.y + b.y) + c.y) + d.y;
        acc.z = ((a.z + b.z) + c.z) + d.z;
        acc.w = ((a.w + b.w) + c.w) + d.w;
    }
    size_t base = (size_t)row * (2 * H_);
    split4_store(g_ctxs + base + c4, g_ctxs + base + H_ + c4, acc);
}

// ===================== front: prep + ins/kv split + W splits (one launch) ====
__global__ void front_kernel(const float* __restrict__ inputs,
                             const float* __restrict__ Ws, const float* __restrict__ sd,
                             const float* __restrict__ bsv,
                             const unsigned char* __restrict__ mraw,
                             const float* __restrict__ W0, const float* __restrict__ W1,
                             const float* __restrict__ W2, const float* __restrict__ W3) {
    const int t = threadIdx.x;
    const int b = blockIdx.x;
    if (b < 4096) {
        // ins + kv split (needs semb: computed inline per 4 cols — cheap? no.
        // semb must be ready: compute redundantly per thread is 4*64 fma = ok)
        size_t i = (size_t)b * 256 + t;
        int row = (int)(i / (H_ / 4)), c4 = (int)(i % (H_ / 4)) * 4;
        float4 v = *reinterpret_cast<const float4*>(inputs + (size_t)row * H_ + c4);
        size_t base = (size_t)row * (2 * H_);
        split4_store(g_ins_s + base + c4, g_ins_s + base + H_ + c4, v);
        float4 sv;
        {
            float s4[4];
#pragma unroll
            for (int e = 0; e < 4; e++) {
                int j = c4 + e;
                float acc = bsv[j];
#pragma unroll
                for (int k = 0; k < DS_; k++) acc = fmaf(Ws[j * DS_ + k], sd[k], acc);
                s4[e] = acc;
            }
            sv.x = s4[0]; sv.y = s4[1]; sv.z = s4[2]; sv.w = s4[3];
        }
        v.x += sv.x; v.y += sv.y; v.z += sv.z; v.w += sv.w;
        split4_store(g_kvin_s + base + c4, g_kvin_s + base + H_ + c4, v);
        return;
    }
    if (b < 8192) {
        int wsel = (b - 4096) >> 10;
        const float* src = (wsel == 0) ? W0 : (wsel == 1) ? W1 : (wsel == 2) ? W2 : W3;
        __nv_bfloat16* dst = (wsel == 0) ? g_Wq_s : (wsel == 1) ? g_Wk_s
                           : (wsel == 2) ? g_Wv_s : g_Wo_s;
        size_t i = (size_t)((b - 4096) & 1023) * 256 + t;
        int row = (int)(i / (H_ / 4)), c4 = (int)(i % (H_ / 4)) * 4;
        float4 v = *reinterpret_cast<const float4*>(src + (size_t)row * H_ + c4);
        size_t base = (size_t)row * (2 * H_);
        split4_store(dst + base + c4, dst + base + H_ + c4, v);
        return;
    }
    // block 8192: mask canonicalize + compact scan
    __shared__ int flag;
    __shared__ int cnts[256];
    if (t == 0) flag = 0;
    __syncthreads();
    int local = 0;
    for (int i = t; i < S_; i += 256)
        if ((i & 3) && mraw[i]) local = 1;
    if (local) atomicOr(&flag, 1);
    __syncthreads();
    if (flag) {
        for (int i = t; i < S_; i += 256) g_maskb[i] = mraw[i] ? 1 : 0;
    } else {
        const int* mi = (const int*)mraw;
        for (int i = t; i < S_; i += 256) g_maskb[i] = mi[i] ? 1 : 0;
    }
    __syncthreads();
    int c0 = 0;
#pragma unroll
    for (int j = 0; j < 16; j++) c0 += g_maskb[t * 16 + j];
    cnts[t] = c0;
    __syncthreads();
    for (int off = 1; off < 256; off <<= 1) {
        int v = 0;
        if (t >= off) v = cnts[t - off];
        __syncthreads();
        cnts[t] += v;
        __syncthreads();
    }
    const int total = cnts[255];
    int p = cnts[t] - c0;
#pragma unroll
    for (int j = 0; j < 16; j++) {
        int s = t * 16 + j;
        if (g_maskb[s]) { g_idx[p] = s; g_pos[s] = p; p++; }
        else            { g_pos[s] = -1; }
    }
    int cp = (total + 127) & ~127;
    if (cp == 0) cp = 128;
    if (cp > S_) cp = S_;
    if (t == 0) { g_cnt = total; g_cntpad = cp; }
    __syncthreads();
    for (int j = total + t; j < cp; j += 256) g_idx[j] = 0;
}

// ===================== split_vt (+ pad zero) =================================
__global__ void split_vt_kernel(const float* __restrict__ V, __nv_bfloat16* __restrict__ dst) {
    __shared__ float tile[32][33];
    const int s0 = blockIdx.x * 32, j0 = blockIdx.y * 32;
    const int t = threadIdx.x;
    const int cnt = g_cnt, cpad = g_cntpad;
#pragma unroll
    for (int e = 0; e < 4; e++) {
        int idx = t + 256 * e;
        int sl = idx >> 5, jl = idx & 31;
        tile[sl][jl] = V[(size_t)(s0 + sl) * H_ + j0 + jl];
    }
    __syncthreads();
#pragma unroll
    for (int e = 0; e < 4; e++) {
        int idx = t + 256 * e;
        int nl = idx >> 5, sl = idx & 31;
        int j = j0 + nl, s = s0 + sl;
        int h = j >> 9, n = j & (HD_ - 1);
        __nv_bfloat16 hi, lo;
        split2(tile[sl][nl], hi, lo);
        size_t base = ((size_t)h * HD_ + n) * (2 * (size_t)S_);
        if (h == 0) {
            int p = g_pos[s];
            if (p >= 0) { dst[base + p] = hi; dst[base + cpad + p] = lo; }
        } else {
            dst[base + s] = hi; dst[base + S_ + s] = lo;
        }
    }
    if (blockIdx.x == 0 && t < 32) {
        int j = j0 + t;
        if ((j >> 9) == 0) {
            int n = j & (HD_ - 1);
            size_t base = (size_t)n * (2 * (size_t)S_);
            __nv_bfloat16 zz = __float2bfloat16(0.f);
            for (int p = cnt; p < cpad; p++) {
                dst[base + p] = zz; dst[base + cpad + p] = zz;
            }
        }
    }
}

// ===================== reductions / softmax / LN =============================
__device__ __forceinline__ float blk_red_max(float v, float* sh) {
    int tid = threadIdx.x;
#pragma unroll
    for (int o = 16; o > 0; o >>= 1) v = fmaxf(v, __shfl_xor_sync(0xffffffffu, v, o));
    if ((tid & 31) == 0) sh[tid >> 5] = v;
    __syncthreads();
    if (tid < 32) {
        float x = (tid < 8) ? sh[tid] : -FLT_MAX;
#pragma unroll
        for (int o = 4; o > 0; o >>= 1) x = fmaxf(x, __shfl_xor_sync(0xffffffffu, x, o));
        if (tid == 0) sh[0] = x;
    }
    __syncthreads();
    float r = sh[0];
    __syncthreads();
    return r;
}
__device__ __forceinline__ float blk_red_sum(float v, float* sh) {
    int tid = threadIdx.x;
#pragma unroll
    for (int o = 16; o > 0; o >>= 1) v += __shfl_xor_sync(0xffffffffu, v, o);
    if ((tid & 31) == 0) sh[tid >> 5] = v;
    __syncthreads();
    if (tid < 32) {
        float x = (tid < 8) ? sh[tid] : 0.f;
#pragma unroll
        for (int o = 4; o > 0; o >>= 1) x += __shfl_xor_sync(0xffffffffu, x, o);
        if (tid == 0) sh[0] = x;
    }
    __syncthreads();
    float r = sh[0];
    __syncthreads();
    return r;
}

__global__ void softmax_split_kernel() {
    __shared__ float sh[8];
    __shared__ float srow[S_];
    const int q = blockIdx.x, h = blockIdx.y, tid = threadIdx.x;
    const float* row = g_logits2 + ((size_t)h * S_ + q) * S_;
    const int cnt  = (h == 0) ? g_cnt    : S_;
    const int cpad = (h == 0) ? g_cntpad : S_;

    float m = -FLT_MAX;
    const int n4 = cnt >> 2;
    const float4* row4 = reinterpret_cast<const float4*>(row);
    for (int i = tid; i < n4; i += 256) {
        float4 v = row4[i];
        int b = i << 2;
        srow[b] = v.x; srow[b + 1] = v.y; srow[b + 2] = v.z; srow[b + 3] = v.w;
        m = fmaxf(m, fmaxf(fmaxf(v.x, v.y), fmaxf(v.z, v.w)));
    }
    for (int i = (n4 << 2) + tid; i < cnt; i += 256) {
        float x = row[i];
        srow[i] = x;
        m = fmaxf(m, x);
    }
    m = blk_red_max(m, sh);

    float sum = 0.f;
    for (int i = tid; i < cnt; i += 256) {
        float e = __expf(srow[i] - m);
        srow[i] = e;
        sum += e;
    }
    sum = blk_red_sum(sum, sh);
    float inv = 1.f / sum;

    __nv_bfloat16* dst = g_Ps2 + ((size_t)h * S_ + q) * (2 * (size_t)S_);
    const int c4 = cpad >> 2;
    for (int i = tid; i < c4; i += 256) {
        int b = i << 2;
        float4 p;
        p.x = (b     < cnt) ? srow[b]     * inv : 0.f;
        p.y = (b + 1 < cnt) ? srow[b + 1] * inv : 0.f;
        p.z = (b + 2 < cnt) ? srow[b + 2] * inv : 0.f;
        p.w = (b + 3 < cnt) ? srow[b + 3] * inv : 0.f;
        split4_store(dst + b, dst + cpad + b, p);
    }
}

__global__ void ln_kernel(const float* __restrict__ inp, const float* __restrict__ lnw,
                          const float* __restrict__ lnb, float* __restrict__ out) {
    __shared__ float sh[8];
    const int s = blockIdx.x, tid = threadIdx.x;
    const float4* o4 = reinterpret_cast<const float4*>(g_out + (size_t)s * H_);
    const float4* x4 = reinterpret_cast<const float4*>(inp + (size_t)s * H_);

    float sum = 0.f, sq = 0.f;
    for (int i = tid; i < H_ / 4; i += 256) {
        float4 a = o4[i], b = x4[i];
        float r0 = a.x + b.x, r1 = a.y + b.y, r2 = a.z + b.z, r3 = a.w + b.w;
        sum += r0 + r1 + r2 + r3;
        sq  += r0 * r0 + r1 * r1 + r2 * r2 + r3 * r3;
    }
    sum = blk_red_sum(sum, sh);
    sq  = blk_red_sum(sq, sh);
    float mu  = sum * (1.f / H_);
    float var = sq * (1.f / H_) - mu * mu;
    float inv = rsqrtf(var + 1e-5f);

    const float4* w4 = reinterpret_cast<const float4*>(lnw);
    const float4* b4 = reinterpret_cast<const float4*>(lnb);
    float4* out4 = reinterpret_cast<float4*>(out + (size_t)s * H_);
    for (int i = tid; i < H_ / 4; i += 256) {
        float4 a = o4[i], b = x4[i], w = w4[i], bb = b4[i];
        float4 r;
        r.x = (a.x + b.x - mu) * inv * w.x + bb.x;
        r.y = (a.y + b.y - mu) * inv * w.y + bb.y;
        r.z = (a.z + b.z - mu) * inv * w.z + bb.z;
        r.w = (a.w + b.w - mu) * inv * w.w + bb.w;
        out4[i] = r;
    }
}

// ===================== launch ================================================
extern "C" void kernel_launch(void* const* d_in, const int* in_sizes, int n_in,
                              void* d_out, int out_size) {
    const float*         inputs = (const float*)d_in[0];
    const float*         sd     = (const float*)d_in[1];
    const unsigned char* mraw   = (const unsigned char*)d_in[2];
    const float*         Wq     = (const float*)d_in[3];
    const float*         Wk     = (const float*)d_in[4];
    const float*         Wv     = (const float*)d_in[5];
    const float*         Wo     = (const float*)d_in[6];
    const float*         Ws     = (const float*)d_in[7];
    const float*         bsv    = (const float*)d_in[8];
    const float*         lnw    = (const float*)d_in[9];
    const float*         lnb    = (const float*)d_in[10];
    float*               out    = (float*)d_out;

    float *pV, *pLog, *pOut;
    int* pIdx;
    __nv_bfloat16 *pQs, *pKs, *pWoS, *pVts, *pCtxS;
    cudaGetSymbolAddress((void**)&pV,    g_V);
    cudaGetSymbolAddress((void**)&pLog,  g_logits2);
    cudaGetSymbolAddress((void**)&pOut,  g_out);
    cudaGetSymbolAddress((void**)&pIdx,  g_idx);
    cudaGetSymbolAddress((void**)&pQs,   g_Qs);
    cudaGetSymbolAddress((void**)&pKs,   g_Ks);
    cudaGetSymbolAddress((void**)&pWoS,  g_Wo_s);
    cudaGetSymbolAddress((void**)&pVts,  g_Vts);
    cudaGetSymbolAddress((void**)&pCtxS, g_ctxs);

    cudaFuncSetAttribute(bf16_gemm_kernel<0>, cudaFuncAttributeMaxDynamicSharedMemorySize, GEMM_SMEM);
    cudaFuncSetAttribute(bf16_gemm_kernel<5>, cudaFuncAttributeMaxDynamicSharedMemorySize, GEMM_SMEM);
    cudaFuncSetAttribute(bf16_gemm_kernel<6>, cudaFuncAttributeMaxDynamicSharedMemorySize, GEMM_SMEM);

    const float inv_sqrt_hd = 1.0f / sqrtf((float)HD_);
    dim3 gp(H_ / 128, S_ / 128, 1);

    // 1: fused front (ins/kv split + W splits + semb + mask scan)
    front_kernel<<<8193, 256>>>(inputs, Ws, sd, bsv, mraw, Wq, Wk, Wv, Wo);
    // 2: merged Q/K/V projection batch
    dim3 gproj(H_ / 128, S_ / 128, 3);
    bf16_gemm_kernel<5><<<gproj, 128, GEMM_SMEM>>>(nullptr, 0, 0, nullptr, 0, 0,
                                                   nullptr, 0, 0, nullptr, K3, 1.f, nullptr, 0);
    // 3: V transpose-split (+ pad zero)
    split_vt_kernel<<<dim3(S_ / 32, H_ / 32), 256>>>(pV, pVts);
    // 4 <- profiled: QK GEMM (z batches heads; z=0 gathers compacted keys)
    dim3 gl(S_ / 128, S_ / 128, NH_);
    bf16_gemm_kernel<0><<<gl, 128, GEMM_SMEM>>>(
        pQs, NH_ * 2 * HD_, 2 * HD_,
        pKs, NH_ * 2 * HD_, 2 * HD_,
        pLog, S_, (size_t)S_ * S_, nullptr,
        KQK, inv_sqrt_hd, pIdx, 0);
    // 5: softmax + P split
    softmax_split_kernel<<<dim3(S_, NH_), 256>>>();
    // 6: PV split-K (6 balanced K-chunks -> fp32 partials)
    dim3 gpv(HD_ / 128, S_ / 128, 6);
    bf16_gemm_kernel<6><<<gpv, 128, GEMM_SMEM>>>(nullptr, 0, 0, nullptr, 0, 0,
                                                 nullptr, 0, 0, nullptr, 0, 1.f, nullptr, 0);
    // 7: fixed-order combine + ctx split
    pv_combine_kernel<<<(S_ * H_ / 4) / 256, 256>>>();
    // 8: output projection
    bf16_gemm_kernel<0><<<gp, 128, GEMM_SMEM>>>(pCtxS, 2 * H_, 0, pWoS, 2 * H_, 0,
                                                pOut, H_, 0, nullptr, K3, 1.f, nullptr, 0);
    // 9: residual + LayerNorm
    ln_kernel<<<S_, 256>>>(inputs, lnw, lnb, out);
}

// round 17
// speedup vs baseline: 2.1858x; 2.1858x over previous
#include <cuda_runtime.h>
#include <cuda_bf16.h>
#include <math.h>
#include <float.h>
#include <stdint.h>

#define S_  4096
#define H_  1024
#define NH_ 2
#define HD_ 512
#define DS_ 64
#define K3  (3 * H_)    // 3072
#define KQK (3 * HD_)   // 1536
#define KPV (3 * S_)    // 12288

// ---------------- scratch (device globals; no allocations allowed) ----------
__device__ float g_semb[H_];
__device__ float g_V[(size_t)S_ * H_];
__device__ float g_logits2[(size_t)NH_ * S_ * S_];
__device__ float g_out[(size_t)S_ * H_];
__device__ unsigned char g_maskb[S_];
__device__ int g_cnt, g_cntpad;
__device__ int g_idx[S_];
__device__ int g_pos[S_];
__device__ float g_pvp[(size_t)6 * S_ * HD_];   // PV split-K partials (fp32)

__device__ __nv_bfloat16 g_ins_s [(size_t)S_ * 2 * H_];
__device__ __nv_bfloat16 g_kvin_s[(size_t)S_ * 2 * H_];
__device__ __nv_bfloat16 g_Wq_s[(size_t)H_ * 2 * H_];
__device__ __nv_bfloat16 g_Wk_s[(size_t)H_ * 2 * H_];
__device__ __nv_bfloat16 g_Wv_s[(size_t)H_ * 2 * H_];
__device__ __nv_bfloat16 g_Wo_s[(size_t)H_ * 2 * H_];
__device__ __nv_bfloat16 g_Qs[(size_t)S_ * NH_ * 2 * HD_];
__device__ __nv_bfloat16 g_Ks[(size_t)S_ * NH_ * 2 * HD_];
__device__ __nv_bfloat16 g_Ps2[(size_t)NH_ * S_ * 2 * S_];
__device__ __nv_bfloat16 g_Vts[(size_t)NH_ * HD_ * 2 * S_];
__device__ __nv_bfloat16 g_ctxs[(size_t)S_ * 2 * H_];

// ===================== helpers ===============================================
__device__ __forceinline__ uint32_t smem_u32(const void* p) {
    uint32_t a;
    asm("{ .reg .u64 t; cvta.to.shared.u64 t, %1; cvt.u32.u64 %0, t; }" : "=r"(a) : "l"(p));
    return a;
}
#define CP_ASYNC16(dst, src) \
    asm volatile("cp.async.cg.shared.global [%0], [%1], 16;" :: "r"(dst), "l"(src))
#define CP_COMMIT() asm volatile("cp.async.commit_group;")
#define CP_WAIT(n)  asm volatile("cp.async.wait_group %0;" :: "n"(n))

__device__ __forceinline__ void ldsm_x4(uint32_t& r0, uint32_t& r1, uint32_t& r2, uint32_t& r3,
                                        uint32_t addr) {
    asm volatile("ldmatrix.sync.aligned.m8n8.x4.shared.b16 {%0,%1,%2,%3}, [%4];"
                 : "=r"(r0), "=r"(r1), "=r"(r2), "=r"(r3) : "r"(addr));
}
__device__ __forceinline__ void mma_16816(float* c, const uint32_t* a, uint32_t b0, uint32_t b1) {
    asm volatile("mma.sync.aligned.m16n8k16.row.col.f32.bf16.bf16.f32 "
                 "{%0,%1,%2,%3}, {%4,%5,%6,%7}, {%8,%9}, {%0,%1,%2,%3};"
                 : "+f"(c[0]), "+f"(c[1]), "+f"(c[2]), "+f"(c[3])
                 : "r"(a[0]), "r"(a[1]), "r"(a[2]), "r"(a[3]), "r"(b0), "r"(b1));
}
__device__ __forceinline__ void split2(float x, __nv_bfloat16& hi, __nv_bfloat16& lo) {
    hi = __float2bfloat16(x);
    lo = __float2bfloat16(x - __bfloat162float(hi));
}
__device__ __forceinline__ void split4_store(__nv_bfloat16* dHi, __nv_bfloat16* dLo, float4 v) {
    __nv_bfloat16 h0, h1, h2, h3, l0, l1, l2, l3;
    split2(v.x, h0, l0); split2(v.y, h1, l1);
    split2(v.z, h2, l2); split2(v.w, h3, l3);
    __nv_bfloat162 ha, hb, la, lb;
    ha.x = h0; ha.y = h1; hb.x = h2; hb.y = h3;
    la.x = l0; la.y = l1; lb.x = l2; lb.y = l3;
    uint2 hp, lp;
    hp.x = *reinterpret_cast<uint32_t*>(&ha); hp.y = *reinterpret_cast<uint32_t*>(&hb);
    lp.x = *reinterpret_cast<uint32_t*>(&la); lp.y = *reinterpret_cast<uint32_t*>(&lb);
    *reinterpret_cast<uint2*>(dHi) = hp;
    *reinterpret_cast<uint2*>(dLo) = lp;
}
__device__ __forceinline__ uint32_t toff(int r, int c8) {
    return (uint32_t)(r * 128 + ((c8 ^ (r & 7)) << 4));
}

// ===================== bf16 HMMA GEMM ========================================
// Logical A' = [Ahi|Alo|Ahi], B' = [Bhi|Bhi|Blo] from physical [hi|lo] via
// per-stage K remap. CTA 128x128, BK=64, 4 warps (64x64), 3-stage cp.async,
// 2 CTA/SM, hoisted row offsets.
// MODE 0: generic fp32 C (+ optional z-gather/early-exit via gidx)
// MODE 5: fused Q/K/V projection (z: 0=Q split, 1=K split, 2=V fp32)
// MODE 6: PV split-K (z: 0,1 = h0 K-chunks; 2..5 = h1 K-chunks) -> fp32 partial
#define GEMM_SMEM (3 * 32768)

template <int MODE>
__global__ __launch_bounds__(128, 2)
void bf16_gemm_kernel(const __nv_bfloat16* __restrict__ A, int lda, size_t sAz,
                      const __nv_bfloat16* __restrict__ B, int ldb, size_t sBz,
                      float* __restrict__ C, int ldc, size_t sCz,
                      __nv_bfloat16* __restrict__ CS,
                      int Kp, float alpha,
                      const int* __restrict__ gidx, int dynz) {
    extern __shared__ char smem[];
    const uint32_t sb = smem_u32(smem);
    const int tid = threadIdx.x, lane = tid & 31, wid = tid >> 5;
    const int row0 = blockIdx.y * 128, col0 = blockIdx.x * 128;
    const int z = blockIdx.z;

    int Kth, s0, NSc;
    const int* gmap = nullptr;
    int hh = 0;
    if (MODE == 6) {
        hh = (z < 2) ? 0 : 1;
        Kth = (hh == 0) ? g_cntpad : S_;
        const int NStot = (3 * Kth) >> 6;
        if (hh == 0) { NSc = NStot >> 1; s0 = z * NSc; }
        else         { NSc = NStot >> 2; s0 = (z - 2) * NSc; }
        A = g_Ps2 + (size_t)hh * S_ * 2 * S_;  lda = 2 * S_;
        B = g_Vts + (size_t)hh * HD_ * 2 * S_; ldb = 2 * S_;
    } else {
        Kth = Kp / 3;
        gmap = (gidx != nullptr && z == 0) ? gidx : nullptr;
        if (gmap != nullptr && col0 >= g_cntpad) return;
        s0 = 0; NSc = (3 * Kth) >> 6;
        if (MODE == 5) {
            A = (z == 0) ? g_ins_s : g_kvin_s;
            B = (z == 0) ? g_Wq_s : (z == 1) ? g_Wk_s : g_Wv_s;
            lda = 2 * H_; ldb = 2 * H_;
        } else {
            A += (size_t)z * sAz;  B += (size_t)z * sBz;  C += (size_t)z * sCz;
        }
    }

    const int wm = wid & 1, wn = wid >> 1;
    const int m_base = wm * 64, n_base = wn * 64;
    const int lr = tid >> 3, lc = tid & 7;
    const int g = lane >> 3, ri = lane & 7;
    const int a_r = ri + ((g & 1) << 3), a_c = g >> 1;
    const int b_r = ri + ((g >> 1) << 3), b_c = g & 1;

    size_t aOff[8], bOff[8];
#pragma unroll
    for (int i = 0; i < 8; i++) {
        int r = lr + 16 * i;
        aOff[i] = (size_t)(row0 + r) * lda + lc * 8;
        int rb_ = col0 + r;
        if (gmap != nullptr) rb_ = gmap[rb_];
        bOff[i] = (size_t)rb_ * ldb + lc * 8;
    }

    float acc[4][8][4];
#pragma unroll
    for (int i = 0; i < 4; i++)
#pragma unroll
        for (int j = 0; j < 8; j++)
#pragma unroll
            for (int k = 0; k < 4; k++) acc[i][j][k] = 0.f;

    auto load_stage = [&](int s) {
        const int k0 = s << 6;
        const int kA = (k0 < 2 * Kth) ? k0 : k0 - 2 * Kth;
        const int kB = (k0 < Kth) ? k0 : k0 - Kth;
        const uint32_t ba = sb + (s % 3) * 32768;
        const uint32_t bb = ba + 16384;
#pragma unroll
        for (int i = 0; i < 8; i++) {
            uint32_t so = toff(lr + 16 * i, lc);
            CP_ASYNC16(ba + so, A + aOff[i] + kA);
            CP_ASYNC16(bb + so, B + bOff[i] + kB);
        }
        CP_COMMIT();
    };

    const int sEnd = s0 + NSc;
    load_stage(s0);
    load_stage(s0 + 1);

    for (int s = s0; s < sEnd; s++) {
        if (s == sEnd - 1) { CP_WAIT(0); } else { CP_WAIT(1); }
        __syncthreads();

        const uint32_t ba = sb + (s % 3) * 32768;
        const uint32_t bb = ba + 16384;
#pragma unroll
        for (int ks = 0; ks < 4; ks++) {
            const int c8k = ks << 1;
            uint32_t afr[4][4];
#pragma unroll
            for (int mi = 0; mi < 4; mi++)
                ldsm_x4(afr[mi][0], afr[mi][1], afr[mi][2], afr[mi][3],
                        ba + toff(m_base + mi * 16 + a_r, c8k + a_c));
            uint32_t bfr[4][4];
#pragma unroll
            for (int p = 0; p < 4; p++)
                ldsm_x4(bfr[p][0], bfr[p][1], bfr[p][2], bfr[p][3],
                        bb + toff(n_base + p * 16 + b_r, c8k + b_c));
#pragma unroll
            for (int mi = 0; mi < 4; mi++)
#pragma unroll
                for (int nj = 0; nj < 8; nj++) {
                    const uint32_t* bp = bfr[nj >> 1];
                    if (nj & 1) mma_16816(acc[mi][nj], afr[mi], bp[2], bp[3]);
                    else        mma_16816(acc[mi][nj], afr[mi], bp[0], bp[1]);
                }
        }
        if (s + 2 < sEnd) load_stage(s + 2);
    }

    // ---- epilogue ----
    const int er = lane >> 2, ec = (lane & 3) << 1;

    auto store_pair = [&](int row, int col, float vx, float vy) {
        if (MODE == 6) {
            float* dst = g_pvp + (size_t)z * S_ * HD_;
            float2 v; v.x = vx; v.y = vy;
            *reinterpret_cast<float2*>(dst + (size_t)row * HD_ + col) = v;
        } else if (MODE == 5) {
            if (z == 2) {
                float2 v; v.x = vx; v.y = vy;
                *reinterpret_cast<float2*>(g_V + (size_t)row * H_ + col) = v;
            } else {
                __nv_bfloat16* dst = (z == 0) ? g_Qs : g_Ks;
                __nv_bfloat16 hx, lx, hy, ly;
                split2(vx, hx, lx);
                split2(vy, hy, ly);
                __nv_bfloat162 h2, l2;
                h2.x = hx; h2.y = hy; l2.x = lx; l2.y = ly;
                int h = col >> 9, jh = col & (HD_ - 1);
                size_t base = (size_t)row * (NH_ * 2 * HD_) + (size_t)h * (2 * HD_);
                *reinterpret_cast<__nv_bfloat162*>(dst + base + jh)        = h2;
                *reinterpret_cast<__nv_bfloat162*>(dst + base + HD_ + jh)  = l2;
            }
        } else {
            float2 v; v.x = vx; v.y = vy;
            *reinterpret_cast<float2*>(C + (size_t)row * ldc + col) = v;
        }
    };

#pragma unroll
    for (int mi = 0; mi < 4; mi++) {
#pragma unroll
        for (int nj = 0; nj < 8; nj++) {
            int row = row0 + m_base + mi * 16 + er;
            int col = col0 + n_base + nj * 8 + ec;
            store_pair(row,     col, acc[mi][nj][0] * alpha, acc[mi][nj][1] * alpha);
            store_pair(row + 8, col, acc[mi][nj][2] * alpha, acc[mi][nj][3] * alpha);
        }
    }
}

// ===================== PV combine: fixed-order sum + ctx split ===============
__global__ void pv_combine_kernel() {
    size_t i = (size_t)blockIdx.x * blockDim.x + threadIdx.x;
    int row = (int)(i / (H_ / 4)), c4 = (int)(i % (H_ / 4)) * 4;
    int h = c4 >> 9, n = c4 & (HD_ - 1);
    size_t off = (size_t)row * HD_ + n;
    float4 acc;
    if (h == 0) {
        const float4 a = *reinterpret_cast<const float4*>(g_pvp + 0 * (size_t)S_ * HD_ + off);
        const float4 b = *reinterpret_cast<const float4*>(g_pvp + 1 * (size_t)S_ * HD_ + off);
        acc.x = a.x + b.x; acc.y = a.y + b.y; acc.z = a.z + b.z; acc.w = a.w + b.w;
    } else {
        const float4 a = *reinterpret_cast<const float4*>(g_pvp + 2 * (size_t)S_ * HD_ + off);
        const float4 b = *reinterpret_cast<const float4*>(g_pvp + 3 * (size_t)S_ * HD_ + off);
        const float4 c = *reinterpret_cast<const float4*>(g_pvp + 4 * (size_t)S_ * HD_ + off);
        const float4 d = *reinterpret_cast<const float4*>(g_pvp + 5 * (size_t)S_ * HD_ + off);
        acc.x = ((a.x + b.x) + c.x) + d.x;
        acc.y = ((a.y + b.y) + c.y) + d.y;
        acc.z = ((a.z + b.z) + c.z) + d.z;
        acc.w = ((a.w + b.w) + c.w) + d.w;
    }
    size_t base = (size_t)row * (2 * H_);
    split4_store(g_ctxs + base + c4, g_ctxs + base + H_ + c4, acc);
}

// ===================== prep: semb (blocks 0-3) + mask scan (block 4) =========
__global__ void prep_kernel(const float* __restrict__ Ws, const float* __restrict__ sd,
                            const float* __restrict__ bsv,
                            const unsigned char* __restrict__ mraw) {
    const int t = threadIdx.x;
    if (blockIdx.x < 4) {
        int j = blockIdx.x * 256 + t;
        float acc = bsv[j];
#pragma unroll
        for (int i = 0; i < DS_; i++) acc = fmaf(Ws[j * DS_ + i], sd[i], acc);
        g_semb[j] = acc;
        return;
    }
    __shared__ int flag;
    __shared__ int cnts[256];
    if (t == 0) flag = 0;
    __syncthreads();
    int local = 0;
    for (int i = t; i < S_; i += 256)
        if ((i & 3) && mraw[i]) local = 1;
    if (local) atomicOr(&flag, 1);
    __syncthreads();
    if (flag) {
        for (int i = t; i < S_; i += 256) g_maskb[i] = mraw[i] ? 1 : 0;
    } else {
        const int* mi = (const int*)mraw;
        for (int i = t; i < S_; i += 256) g_maskb[i] = mi[i] ? 1 : 0;
    }
    __syncthreads();
    int c0 = 0;
#pragma unroll
    for (int j = 0; j < 16; j++) c0 += g_maskb[t * 16 + j];
    cnts[t] = c0;
    __syncthreads();
    for (int off = 1; off < 256; off <<= 1) {
        int v = 0;
        if (t >= off) v = cnts[t - off];
        __syncthreads();
        cnts[t] += v;
        __syncthreads();
    }
    const int total = cnts[255];
    int p = cnts[t] - c0;
#pragma unroll
    for (int j = 0; j < 16; j++) {
        int s = t * 16 + j;
        if (g_maskb[s]) { g_idx[p] = s; g_pos[s] = p; p++; }
        else            { g_pos[s] = -1; }
    }
    int cp = (total + 127) & ~127;
    if (cp == 0) cp = 128;
    if (cp > S_) cp = S_;
    if (t == 0) { g_cnt = total; g_cntpad = cp; }
    __syncthreads();
    for (int j = total + t; j < cp; j += 256) g_idx[j] = 0;
}

// ===================== split kernels (vectorized, physical [hi|lo]) ==========
__global__ void split_ins_kv_kernel(const float* __restrict__ src,
                                    __nv_bfloat16* __restrict__ dIns,
                                    __nv_bfloat16* __restrict__ dKv) {
    size_t i = (size_t)blockIdx.x * blockDim.x + threadIdx.x;
    int row = (int)(i / (H_ / 4)), c4 = (int)(i % (H_ / 4)) * 4;
    float4 v = *reinterpret_cast<const float4*>(src + (size_t)row * H_ + c4);
    size_t base = (size_t)row * (2 * H_);
    split4_store(dIns + base + c4, dIns + base + H_ + c4, v);
    const float4 sv = *reinterpret_cast<const float4*>(g_semb + c4);
    v.x += sv.x; v.y += sv.y; v.z += sv.z; v.w += sv.w;
    split4_store(dKv + base + c4, dKv + base + H_ + c4, v);
}

__global__ void split_w4_kernel(const float* __restrict__ W0, const float* __restrict__ W1,
                                const float* __restrict__ W2, const float* __restrict__ W3,
                                __nv_bfloat16* __restrict__ D0, __nv_bfloat16* __restrict__ D1,
                                __nv_bfloat16* __restrict__ D2, __nv_bfloat16* __restrict__ D3) {
    const float* src = (blockIdx.y == 0) ? W0 : (blockIdx.y == 1) ? W1 : (blockIdx.y == 2) ? W2 : W3;
    __nv_bfloat16* dst = (blockIdx.y == 0) ? D0 : (blockIdx.y == 1) ? D1 : (blockIdx.y == 2) ? D2 : D3;
    size_t i = (size_t)blockIdx.x * blockDim.x + threadIdx.x;
    int row = (int)(i / (H_ / 4)), c4 = (int)(i % (H_ / 4)) * 4;
    float4 v = *reinterpret_cast<const float4*>(src + (size_t)row * H_ + c4);
    size_t base = (size_t)row * (2 * H_);
    split4_store(dst + base + c4, dst + base + H_ + c4, v);
}

// V transpose-split (+ pad zero)
__global__ void split_vt_kernel(const float* __restrict__ V, __nv_bfloat16* __restrict__ dst) {
    __shared__ float tile[32][33];
    const int s0 = blockIdx.x * 32, j0 = blockIdx.y * 32;
    const int t = threadIdx.x;
    const int cnt = g_cnt, cpad = g_cntpad;
#pragma unroll
    for (int e = 0; e < 4; e++) {
        int idx = t + 256 * e;
        int sl = idx >> 5, jl = idx & 31;
        tile[sl][jl] = V[(size_t)(s0 + sl) * H_ + j0 + jl];
    }
    __syncthreads();
#pragma unroll
    for (int e = 0; e < 4; e++) {
        int idx = t + 256 * e;
        int nl = idx >> 5, sl = idx & 31;
        int j = j0 + nl, s = s0 + sl;
        int h = j >> 9, n = j & (HD_ - 1);
        __nv_bfloat16 hi, lo;
        split2(tile[sl][nl], hi, lo);
        size_t base = ((size_t)h * HD_ + n) * (2 * (size_t)S_);
        if (h == 0) {
            int p = g_pos[s];
            if (p >= 0) { dst[base + p] = hi; dst[base + cpad + p] = lo; }
        } else {
            dst[base + s] = hi; dst[base + S_ + s] = lo;
        }
    }
    if (blockIdx.x == 0 && t < 32) {
        int j = j0 + t;
        if ((j >> 9) == 0) {
            int n = j & (HD_ - 1);
            size_t base = (size_t)n * (2 * (size_t)S_);
            __nv_bfloat16 zz = __float2bfloat16(0.f);
            for (int p = cnt; p < cpad; p++) {
                dst[base + p] = zz; dst[base + cpad + p] = zz;
            }
        }
    }
}

// ===================== reductions / softmax / LN =============================
__device__ __forceinline__ float blk_red_max(float v, float* sh) {
    int tid = threadIdx.x;
#pragma unroll
    for (int o = 16; o > 0; o >>= 1) v = fmaxf(v, __shfl_xor_sync(0xffffffffu, v, o));
    if ((tid & 31) == 0) sh[tid >> 5] = v;
    __syncthreads();
    if (tid < 32) {
        float x = (tid < 8) ? sh[tid] : -FLT_MAX;
#pragma unroll
        for (int o = 4; o > 0; o >>= 1) x = fmaxf(x, __shfl_xor_sync(0xffffffffu, x, o));
        if (tid == 0) sh[0] = x;
    }
    __syncthreads();
    float r = sh[0];
    __syncthreads();
    return r;
}
__device__ __forceinline__ float blk_red_sum(float v, float* sh) {
    int tid = threadIdx.x;
#pragma unroll
    for (int o = 16; o > 0; o >>= 1) v += __shfl_xor_sync(0xffffffffu, v, o);
    if ((tid & 31) == 0) sh[tid >> 5] = v;
    __syncthreads();
    if (tid < 32) {
        float x = (tid < 8) ? sh[tid] : 0.f;
#pragma unroll
        for (int o = 4; o > 0; o >>= 1) x += __shfl_xor_sync(0xffffffffu, x, o);
        if (tid == 0) sh[0] = x;
    }
    __syncthreads();
    float r = sh[0];
    __syncthreads();
    return r;
}

__global__ void softmax_split_kernel() {
    __shared__ float sh[8];
    __shared__ float srow[S_];
    const int q = blockIdx.x, h = blockIdx.y, tid = threadIdx.x;
    const float* row = g_logits2 + ((size_t)h * S_ + q) * S_;
    const int cnt  = (h == 0) ? g_cnt    : S_;
    const int cpad = (h == 0) ? g_cntpad : S_;

    float m = -FLT_MAX;
    const int n4 = cnt >> 2;
    const float4* row4 = reinterpret_cast<const float4*>(row);
    for (int i = tid; i < n4; i += 256) {
        float4 v = row4[i];
        int b = i << 2;
        srow[b] = v.x; srow[b + 1] = v.y; srow[b + 2] = v.z; srow[b + 3] = v.w;
        m = fmaxf(m, fmaxf(fmaxf(v.x, v.y), fmaxf(v.z, v.w)));
    }
    for (int i = (n4 << 2) + tid; i < cnt; i += 256) {
        float x = row[i];
        srow[i] = x;
        m = fmaxf(m, x);
    }
    m = blk_red_max(m, sh);

    float sum = 0.f;
    for (int i = tid; i < cnt; i += 256) {
        float e = __expf(srow[i] - m);
        srow[i] = e;
        sum += e;
    }
    sum = blk_red_sum(sum, sh);
    float inv = 1.f / sum;

    __nv_bfloat16* dst = g_Ps2 + ((size_t)h * S_ + q) * (2 * (size_t)S_);
    const int c4 = cpad >> 2;
    for (int i = tid; i < c4; i += 256) {
        int b = i << 2;
        float4 p;
        p.x = (b     < cnt) ? srow[b]     * inv : 0.f;
        p.y = (b + 1 < cnt) ? srow[b + 1] * inv : 0.f;
        p.z = (b + 2 < cnt) ? srow[b + 2] * inv : 0.f;
        p.w = (b + 3 < cnt) ? srow[b + 3] * inv : 0.f;
        split4_store(dst + b, dst + cpad + b, p);
    }
}

__global__ void ln_kernel(const float* __restrict__ inp, const float* __restrict__ lnw,
                          const float* __restrict__ lnb, float* __restrict__ out) {
    __shared__ float sh[8];
    const int s = blockIdx.x, tid = threadIdx.x;
    const float4* o4 = reinterpret_cast<const float4*>(g_out + (size_t)s * H_);
    const float4* x4 = reinterpret_cast<const float4*>(inp + (size_t)s * H_);

    float sum = 0.f, sq = 0.f;
    for (int i = tid; i < H_ / 4; i += 256) {
        float4 a = o4[i], b = x4[i];
        float r0 = a.x + b.x, r1 = a.y + b.y, r2 = a.z + b.z, r3 = a.w + b.w;
        sum += r0 + r1 + r2 + r3;
        sq  += r0 * r0 + r1 * r1 + r2 * r2 + r3 * r3;
    }
    sum = blk_red_sum(sum, sh);
    sq  = blk_red_sum(sq, sh);
    float mu  = sum * (1.f / H_);
    float var = sq * (1.f / H_) - mu * mu;
    float inv = rsqrtf(var + 1e-5f);

    const float4* w4 = reinterpret_cast<const float4*>(lnw);
    const float4* b4 = reinterpret_cast<const float4*>(lnb);
    float4* out4 = reinterpret_cast<float4*>(out + (size_t)s * H_);
    for (int i = tid; i < H_ / 4; i += 256) {
        float4 a = o4[i], b = x4[i], w = w4[i], bb = b4[i];
        float4 r;
        r.x = (a.x + b.x - mu) * inv * w.x + bb.x;
        r.y = (a.y + b.y - mu) * inv * w.y + bb.y;
        r.z = (a.z + b.z - mu) * inv * w.z + bb.z;
        r.w = (a.w + b.w - mu) * inv * w.w + bb.w;
        out4[i] = r;
    }
}

// ===================== launch ================================================
extern "C" void kernel_launch(void* const* d_in, const int* in_sizes, int n_in,
                              void* d_out, int out_size) {
    const float*         inputs = (const float*)d_in[0];
    const float*         sd     = (const float*)d_in[1];
    const unsigned char* mraw   = (const unsigned char*)d_in[2];
    const float*         Wq     = (const float*)d_in[3];
    const float*         Wk     = (const float*)d_in[4];
    const float*         Wv     = (const float*)d_in[5];
    const float*         Wo     = (const float*)d_in[6];
    const float*         Ws     = (const float*)d_in[7];
    const float*         bsv    = (const float*)d_in[8];
    const float*         lnw    = (const float*)d_in[9];
    const float*         lnb    = (const float*)d_in[10];
    float*               out    = (float*)d_out;

    float *pV, *pLog, *pOut;
    int* pIdx;
    __nv_bfloat16 *pInsS, *pKvS, *pWqS, *pWkS, *pWvS, *pWoS, *pQs, *pKs, *pVts, *pCtxS;
    cudaGetSymbolAddress((void**)&pV,    g_V);
    cudaGetSymbolAddress((void**)&pLog,  g_logits2);
    cudaGetSymbolAddress((void**)&pOut,  g_out);
    cudaGetSymbolAddress((void**)&pIdx,  g_idx);
    cudaGetSymbolAddress((void**)&pInsS, g_ins_s);
    cudaGetSymbolAddress((void**)&pKvS,  g_kvin_s);
    cudaGetSymbolAddress((void**)&pWqS,  g_Wq_s);
    cudaGetSymbolAddress((void**)&pWkS,  g_Wk_s);
    cudaGetSymbolAddress((void**)&pWvS,  g_Wv_s);
    cudaGetSymbolAddress((void**)&pWoS,  g_Wo_s);
    cudaGetSymbolAddress((void**)&pQs,   g_Qs);
    cudaGetSymbolAddress((void**)&pKs,   g_Ks);
    cudaGetSymbolAddress((void**)&pVts,  g_Vts);
    cudaGetSymbolAddress((void**)&pCtxS, g_ctxs);

    cudaFuncSetAttribute(bf16_gemm_kernel<0>, cudaFuncAttributeMaxDynamicSharedMemorySize, GEMM_SMEM);
    cudaFuncSetAttribute(bf16_gemm_kernel<5>, cudaFuncAttributeMaxDynamicSharedMemorySize, GEMM_SMEM);
    cudaFuncSetAttribute(bf16_gemm_kernel<6>, cudaFuncAttributeMaxDynamicSharedMemorySize, GEMM_SMEM);

    const float inv_sqrt_hd = 1.0f / sqrtf((float)HD_);
    dim3 gp(H_ / 128, S_ / 128, 1);

    prep_kernel<<<5, 256>>>(Ws, sd, bsv, mraw);                                  // 1
    split_ins_kv_kernel<<<(S_ * H_ / 4) / 256, 256>>>(inputs, pInsS, pKvS);      // 2
    split_w4_kernel<<<dim3((H_ * H_ / 4) / 256, 4), 256>>>(Wq, Wk, Wv, Wo,
                                                           pWqS, pWkS, pWvS, pWoS); // 3
    // 4 <- profiled: merged Q/K/V projection batch
    dim3 gproj(H_ / 128, S_ / 128, 3);
    bf16_gemm_kernel<5><<<gproj, 128, GEMM_SMEM>>>(nullptr, 0, 0, nullptr, 0, 0,
                                                   nullptr, 0, 0, nullptr, K3, 1.f, nullptr, 0);
    split_vt_kernel<<<dim3(S_ / 32, H_ / 32), 256>>>(pV, pVts);                  // 5

    // QK: z batches heads; z=0 gathers compacted keys + early-exits past cntpad
    dim3 gl(S_ / 128, S_ / 128, NH_);
    bf16_gemm_kernel<0><<<gl, 128, GEMM_SMEM>>>(
        pQs, NH_ * 2 * HD_, 2 * HD_,
        pKs, NH_ * 2 * HD_, 2 * HD_,
        pLog, S_, (size_t)S_ * S_, nullptr,
        KQK, inv_sqrt_hd, pIdx, 0);                                              // 6
    softmax_split_kernel<<<dim3(S_, NH_), 256>>>();                              // 7
    // PV split-K (6 balanced K-chunks -> fp32 partials)
    dim3 gpv(HD_ / 128, S_ / 128, 6);
    bf16_gemm_kernel<6><<<gpv, 128, GEMM_SMEM>>>(nullptr, 0, 0, nullptr, 0, 0,
                                                 nullptr, 0, 0, nullptr, 0, 1.f, nullptr, 0); // 8
    pv_combine_kernel<<<(S_ * H_ / 4) / 256, 256>>>();                           // 9
    bf16_gemm_kernel<0><<<gp, 128, GEMM_SMEM>>>(pCtxS, 2 * H_, 0, pWoS, 2 * H_, 0,
                                                pOut, H_, 0, nullptr, K3, 1.f, nullptr, 0); // 10
    ln_kernel<<<S_, 256>>>(inputs, lnw, lnb, out);                               // 11
}